// round 11
// baseline (speedup 1.0000x reference)
#include <cuda_runtime.h>
#include <cuda_bf16.h>
#include <cstdint>
#include <math.h>

#define N1_TOT 65536   // 4 * 16384 fine points
#define N2_TOT 16384   // 4 * 4096 coarse points
#define NPS1   16384
#define NPS2   4096
#define CIN    512
#define COUT   256

typedef unsigned long long u64;

// scratch for h2 (branch-2 features), 16 MB
__device__ float g_h2[N2_TOT * COUT];

// ===========================================================================
// helpers
// ===========================================================================
__device__ __forceinline__ uint32_t smem_to_u32(const void* smem_ptr) {
    uint32_t addr;
    asm("{ .reg .u64 tmp; cvta.to.shared.u64 tmp, %1; cvt.u32.u64 %0, tmp; }"
        : "=r"(addr) : "l"(smem_ptr));
    return addr;
}
__device__ __forceinline__ uint32_t bf16x2_rn(float lo, float hi) {
    uint32_t r;
    asm("cvt.rn.bf16x2.f32 %0, %1, %2;" : "=r"(r) : "f"(hi), "f"(lo));
    return r;
}
__device__ __forceinline__ float bf_lo_f(uint32_t p) { return __uint_as_float(p << 16); }
__device__ __forceinline__ float bf_hi_f(uint32_t p) { return __uint_as_float(p & 0xffff0000u); }
__device__ __forceinline__ u64 packu64(uint32_t lo, uint32_t hi) {
    return ((u64)hi << 32) | (u64)lo;
}
#define STS64(smem_addr, val) \
    asm volatile("st.shared.b64 [%0], %1;" :: "r"(smem_addr), "l"(val) : "memory")

__device__ __forceinline__ void ldm_x4(uint32_t addr, uint32_t* r) {
    asm volatile("ldmatrix.sync.aligned.m8n8.x4.shared.b16 {%0,%1,%2,%3}, [%4];"
        : "=r"(r[0]), "=r"(r[1]), "=r"(r[2]), "=r"(r[3]) : "r"(addr));
}
__device__ __forceinline__ void mma_bf16(float* c, const uint32_t* a, const uint32_t* b) {
    asm volatile(
        "mma.sync.aligned.m16n8k16.row.col.f32.bf16.bf16.f32 "
        "{%0,%1,%2,%3}, {%4,%5,%6,%7}, {%8,%9}, {%0,%1,%2,%3};"
        : "+f"(c[0]), "+f"(c[1]), "+f"(c[2]), "+f"(c[3])
        : "r"(a[0]), "r"(a[1]), "r"(a[2]), "r"(a[3]), "r"(b[0]), "r"(b[1]));
}

// ===========================================================================
// Tensor-core (mma.sync bf16) GEMM + BN + ReLU, split-precision,
// DOUBLE-BUFFERED: convert chunk c+1 while MMA-ing chunk c.
//   C[m, n] = relu(alpha[n] * (sum_k A[m,k] * W[n,k]) + beta[n])
// A ~= Ahi + Alo, W ~= Whi + Wlo (bf16); acc = Ahi*Whi + Ahi*Wlo + Alo*Whi.
// Tile 128(M) x 128(N), BK=32. 8 warps (2x4), warp tile 64x32.
// smem pitch 80 B; dynamic smem 2 stages x 40 KB.
// ===========================================================================
#define SPITCH 80
#define STAGE_BYTES (4 * 128 * SPITCH)   // 40960

__global__ void __launch_bounds__(256, 2)
gemm_mma(const float* __restrict__ A, const float* __restrict__ W,
         const float* __restrict__ bias, const float* __restrict__ gam,
         const float* __restrict__ bet, const float* __restrict__ mu,
         const float* __restrict__ var, float* __restrict__ C, int Kd)
{
    extern __shared__ __align__(16) uint8_t dsm[];
    __shared__ float s_al[128];
    __shared__ float s_be[128];

    const int tid  = threadIdx.x;
    const int wid  = tid >> 5;
    const int lane = tid & 31;
    const int bm   = blockIdx.x;
    const int by   = blockIdx.y;

    if (tid < 128) {
        int c = by * 128 + tid;
        float s = gam[c] * rsqrtf(var[c] + 1e-5f);
        s_al[tid] = s;
        s_be[tid] = (bias[c] - mu[c]) * s + bet[c];
    }

    const uint32_t sbase = smem_to_u32(dsm);
    // per-stage matrix bases
    // stage s: Ahi +0, Alo +10240, Whi +20480, Wlo +30720

    // loader mapping: thread -> row tid/2 (0..127), col half (tid&1)*16
    const int lrow = tid >> 1;
    const int lcol = (tid & 1) * 16;
    const float* srcA0 = A + ((size_t)(bm * 128 + lrow)) * Kd + lcol;
    const float* srcW0 = W + ((size_t)(by * 128 + lrow)) * Kd + lcol;
    const uint32_t stA = lrow * SPITCH + lcol * 2;

    // warp tiling
    const int warp_m = wid >> 2;   // 0-1
    const int warp_n = wid & 3;    // 0-3
    const int a_row = (lane & 15);
    const int a_ko  = (lane >> 4) * 8;
    const int b_n   = ((lane >> 4) & 1) * 8 + (lane & 7);
    const int b_ko  = ((lane >> 3) & 1) * 8;

    float acc[4][4][4];
#pragma unroll
    for (int mt = 0; mt < 4; mt++)
#pragma unroll
        for (int j = 0; j < 4; j++)
#pragma unroll
            for (int e = 0; e < 4; e++) acc[mt][j][e] = 0.0f;

    const int nch = Kd >> 5;

    // ---- convert chunk 0 into stage 0 ----
    {
        const uint32_t sg = sbase;
        const float* sa  = srcA0;
        const float* sw_ = srcW0;
#pragma unroll
        for (int j = 0; j < 4; j++) {
            float4 v = *(const float4*)(sa + 4 * j);
            uint32_t h0 = bf16x2_rn(v.x, v.y);
            uint32_t h1 = bf16x2_rn(v.z, v.w);
            uint32_t l0 = bf16x2_rn(v.x - bf_lo_f(h0), v.y - bf_hi_f(h0));
            uint32_t l1 = bf16x2_rn(v.z - bf_lo_f(h1), v.w - bf_hi_f(h1));
            uint32_t ad = stA + 8 * j;
            STS64(sg + ad, packu64(h0, h1));                // Ahi
            STS64(sg + 10240 + ad, packu64(l0, l1));        // Alo
            float4 u = *(const float4*)(sw_ + 4 * j);
            uint32_t H0 = bf16x2_rn(u.x, u.y);
            uint32_t H1 = bf16x2_rn(u.z, u.w);
            uint32_t L0 = bf16x2_rn(u.x - bf_lo_f(H0), u.y - bf_hi_f(H0));
            uint32_t L1 = bf16x2_rn(u.z - bf_lo_f(H1), u.w - bf_hi_f(H1));
            STS64(sg + 20480 + ad, packu64(H0, H1));        // Whi
            STS64(sg + 30720 + ad, packu64(L0, L1));        // Wlo
        }
    }
    __syncthreads();

    for (int c = 0; c < nch; c++) {
        const uint32_t sg = sbase + (uint32_t)(c & 1) * STAGE_BYTES;

        // ---- compute chunk c: 2 k16 steps ----
#pragma unroll
        for (int ks = 0; ks < 2; ks++) {
            const uint32_t a_off = (uint32_t)((warp_m * 64 + a_row) * SPITCH + (ks * 16 + a_ko) * 2);
            const uint32_t b_off = (uint32_t)((warp_n * 32 + b_n) * SPITCH + (ks * 16 + b_ko) * 2);

            uint32_t ah[4][4], bh[2][4], bl[2][4];
#pragma unroll
            for (int mt = 0; mt < 4; mt++)
                ldm_x4(sg + a_off + mt * 16 * SPITCH, ah[mt]);
#pragma unroll
            for (int ng = 0; ng < 2; ng++) {
                ldm_x4(sg + 20480 + b_off + ng * 16 * SPITCH, bh[ng]);
                ldm_x4(sg + 30720 + b_off + ng * 16 * SPITCH, bl[ng]);
            }

#pragma unroll
            for (int mt = 0; mt < 4; mt++)
#pragma unroll
                for (int j = 0; j < 4; j++) {
                    mma_bf16(acc[mt][j], ah[mt], &bh[j >> 1][(j & 1) * 2]);
                    mma_bf16(acc[mt][j], ah[mt], &bl[j >> 1][(j & 1) * 2]);
                }

#pragma unroll
            for (int mt = 0; mt < 4; mt++)
                ldm_x4(sg + 10240 + a_off + mt * 16 * SPITCH, ah[mt]);  // Alo
#pragma unroll
            for (int mt = 0; mt < 4; mt++)
#pragma unroll
                for (int j = 0; j < 4; j++)
                    mma_bf16(acc[mt][j], ah[mt], &bh[j >> 1][(j & 1) * 2]);
        }

        // ---- convert chunk c+1 into the other stage (overlaps other warps' MMAs) ----
        if (c + 1 < nch) {
            const uint32_t sn = sbase + (uint32_t)((c + 1) & 1) * STAGE_BYTES;
            const int kt = (c + 1) << 5;
            const float* sa  = srcA0 + kt;
            const float* sw_ = srcW0 + kt;
#pragma unroll
            for (int j = 0; j < 4; j++) {
                float4 v = *(const float4*)(sa + 4 * j);
                uint32_t h0 = bf16x2_rn(v.x, v.y);
                uint32_t h1 = bf16x2_rn(v.z, v.w);
                uint32_t l0 = bf16x2_rn(v.x - bf_lo_f(h0), v.y - bf_hi_f(h0));
                uint32_t l1 = bf16x2_rn(v.z - bf_lo_f(h1), v.w - bf_hi_f(h1));
                uint32_t ad = stA + 8 * j;
                STS64(sn + ad, packu64(h0, h1));
                STS64(sn + 10240 + ad, packu64(l0, l1));
                float4 u = *(const float4*)(sw_ + 4 * j);
                uint32_t H0 = bf16x2_rn(u.x, u.y);
                uint32_t H1 = bf16x2_rn(u.z, u.w);
                uint32_t L0 = bf16x2_rn(u.x - bf_lo_f(H0), u.y - bf_hi_f(H0));
                uint32_t L1 = bf16x2_rn(u.z - bf_lo_f(H1), u.w - bf_hi_f(H1));
                STS64(sn + 20480 + ad, packu64(H0, H1));
                STS64(sn + 30720 + ad, packu64(L0, L1));
            }
        }
        __syncthreads();
    }

    // ---- epilogue: BN + ReLU, direct global stores ----
#pragma unroll
    for (int mt = 0; mt < 4; mt++) {
        int r0 = bm * 128 + warp_m * 64 + mt * 16 + (lane >> 2);
#pragma unroll
        for (int j = 0; j < 4; j++) {
            int lc = warp_n * 32 + j * 8 + (lane & 3) * 2;
            int gc = by * 128 + lc;
            float a0 = s_al[lc], a1 = s_al[lc + 1];
            float e0 = s_be[lc], e1 = s_be[lc + 1];
            float2 o;
            o.x = fmaxf(fmaf(acc[mt][j][0], a0, e0), 0.f);
            o.y = fmaxf(fmaf(acc[mt][j][1], a1, e1), 0.f);
            *(float2*)(C + (size_t)r0 * 256 + gc) = o;
            o.x = fmaxf(fmaf(acc[mt][j][2], a0, e0), 0.f);
            o.y = fmaxf(fmaf(acc[mt][j][3], a1, e1), 0.f);
            *(float2*)(C + (size_t)(r0 + 8) * 256 + gc) = o;
        }
    }
}

// ===========================================================================
// interp helpers (packed f32x2)
// ===========================================================================
__device__ __forceinline__ u64 fma2(u64 a, u64 b, u64 c) {
    u64 d;
    asm("fma.rn.f32x2 %0, %1, %2, %3;" : "=l"(d) : "l"(a), "l"(b), "l"(c));
    return d;
}
__device__ __forceinline__ u64 pack2(float x) {
    u64 d;
    asm("mov.b64 %0, {%1, %1};" : "=l"(d) : "r"(__float_as_uint(x)));
    return d;
}
__device__ __forceinline__ u64 packf2(float a, float b) {
    u64 d;
    asm("mov.b64 %0, {%1, %2};" : "=l"(d) : "r"(__float_as_uint(a)), "r"(__float_as_uint(b)));
    return d;
}
__device__ __forceinline__ float lo32(u64 v) { return __uint_as_float((unsigned)(v & 0xffffffffull)); }
__device__ __forceinline__ float hi32(u64 v) { return __uint_as_float((unsigned)(v >> 32)); }

// ---------------------------------------------------------------------------
// kNN (k=3) interpolation + accumulate into out.
// Quad screening with top-4 quad tracker, then exact re-evaluation of the 16
// candidate points (provably exact selection; see round-4 notes).
// ---------------------------------------------------------------------------
#define PTILE 512            // points per tile
#define QPT   128            // quads per tile

__global__ void __launch_bounds__(256)
interp_kernel(const float* __restrict__ p1, const float* __restrict__ p2,
              const float* __restrict__ h2, float* __restrict__ out)
{
    __shared__ ulonglong2 sX[QPT], sY[QPT], sZ[QPT], sP[QPT];  // 8 KB
    __shared__ float sq[256 * 3];
    __shared__ float sw[3][256];
    __shared__ int   si[3][256];

    const int tid = threadIdx.x;
    const int q0 = blockIdx.x * 256;
    const int scene = q0 / NPS1;

    for (int j = tid; j < 256 * 3; j += 256) sq[j] = p1[(size_t)q0 * 3 + j];
    __syncthreads();
    const float qx = sq[tid * 3 + 0];
    const float qy = sq[tid * 3 + 1];
    const float qz = sq[tid * 3 + 2];
    const u64 qxp = pack2(-2.0f * qx);
    const u64 qyp = pack2(-2.0f * qy);
    const u64 qzp = pack2(-2.0f * qz);

    float c0 = 3.4e38f, c1 = 3.4e38f, c2 = 3.4e38f, c3 = 3.4e38f;
    int   g0 = 0, g1 = 0, g2 = 0, g3 = 0;

    const float* pb = p2 + (size_t)scene * NPS2 * 3;

    for (int t0 = 0; t0 < NPS2; t0 += PTILE) {
        __syncthreads();
        for (int j = tid; j < QPT; j += 256) {
            const float* pp = pb + (size_t)(t0 + 4 * j) * 3;
            float4 fa = *(const float4*)(pp + 0);
            float4 fb = *(const float4*)(pp + 4);
            float4 fc = *(const float4*)(pp + 8);
            float x0 = fa.x, y0 = fa.y, z0 = fa.z;
            float x1 = fa.w, y1 = fb.x, z1 = fb.y;
            float x2 = fb.z, y2 = fb.w, z2 = fc.x;
            float x3 = fc.y, y3 = fc.z, z3 = fc.w;
            sX[j] = make_ulonglong2(packf2(x0, x1), packf2(x2, x3));
            sY[j] = make_ulonglong2(packf2(y0, y1), packf2(y2, y3));
            sZ[j] = make_ulonglong2(packf2(z0, z1), packf2(z2, z3));
            float p0 = fmaf(x0, x0, fmaf(y0, y0, z0 * z0));
            float p1_ = fmaf(x1, x1, fmaf(y1, y1, z1 * z1));
            float p2_ = fmaf(x2, x2, fmaf(y2, y2, z2 * z2));
            float p3 = fmaf(x3, x3, fmaf(y3, y3, z3 * z3));
            sP[j] = make_ulonglong2(packf2(p0, p1_), packf2(p2_, p3));
        }
        __syncthreads();

        const int qbase = t0 >> 2;
#pragma unroll 4
        for (int j = 0; j < QPT; j++) {
            ulonglong2 X = sX[j];
            ulonglong2 Y = sY[j];
            ulonglong2 Z = sZ[j];
            ulonglong2 P = sP[j];
            u64 dA = fma2(qxp, X.x, fma2(qyp, Y.x, fma2(qzp, Z.x, P.x)));
            u64 dB = fma2(qxp, X.y, fma2(qyp, Y.y, fma2(qzp, Z.y, P.y)));
            float m = fminf(fminf(lo32(dA), hi32(dA)), fminf(lo32(dB), hi32(dB)));
            if (m < c3) {
                int qi = qbase + j;
                if (m < c2) {
                    c3 = c2; g3 = g2;
                    if (m < c1) {
                        c2 = c1; g2 = g1;
                        if (m < c0) { c1 = c0; g1 = g0; c0 = m; g0 = qi; }
                        else        { c1 = m;  g1 = qi; }
                    } else { c2 = m; g2 = qi; }
                } else { c3 = m; g3 = qi; }
            }
        }
    }

    // exact re-evaluation of the 16 candidate points
    float b0 = 3.4e38f, b1 = 3.4e38f, b2v = 3.4e38f;
    int   i0 = 0, i1 = 0, i2 = 0;
    int quads[4] = {g0, g1, g2, g3};
#pragma unroll
    for (int cq = 0; cq < 4; cq++) {
        int base = quads[cq] * 4;
#pragma unroll
        for (int u = 0; u < 4; u++) {
            int pi = base + u;
            float dx = qx - pb[pi * 3 + 0];
            float dy = qy - pb[pi * 3 + 1];
            float dz = qz - pb[pi * 3 + 2];
            float d = fmaf(dx, dx, fmaf(dy, dy, dz * dz));
            if (d < b2v) {
                if (d < b1) {
                    b2v = b1; i2 = i1;
                    if (d < b0) { b1 = b0; i1 = i0; b0 = d; i0 = pi; }
                    else        { b1 = d;  i1 = pi; }
                } else { b2v = d; i2 = pi; }
            }
        }
    }

    float w0 = 1.0f / (sqrtf(fmaxf(b0, 1e-12f)) + 1e-8f);
    float w1 = 1.0f / (sqrtf(fmaxf(b1, 1e-12f)) + 1e-8f);
    float w2 = 1.0f / (sqrtf(fmaxf(b2v, 1e-12f)) + 1e-8f);
    float ws = w0 + w1 + w2;
    w0 /= ws; w1 /= ws; w2 /= ws;

    sw[0][tid] = w0; sw[1][tid] = w1; sw[2][tid] = w2;
    si[0][tid] = i0; si[1][tid] = i1; si[2][tid] = i2;
    __syncthreads();

    // phase 2: warp-parallel weighted gather, 2 queries in flight per warp
    const float* h2b = h2 + (size_t)scene * NPS2 * COUT;
    const int warp = tid >> 5, lane = tid & 31;
    for (int q = warp * 2; q < 256; q += 16) {
        float a0 = sw[0][q],     a1 = sw[1][q],     a2 = sw[2][q];
        float d0 = sw[0][q + 1], d1 = sw[1][q + 1], d2 = sw[2][q + 1];
        const float4* f0 = (const float4*)(h2b + (size_t)si[0][q] * COUT);
        const float4* f1 = (const float4*)(h2b + (size_t)si[1][q] * COUT);
        const float4* f2 = (const float4*)(h2b + (size_t)si[2][q] * COUT);
        const float4* e0 = (const float4*)(h2b + (size_t)si[0][q + 1] * COUT);
        const float4* e1 = (const float4*)(h2b + (size_t)si[1][q + 1] * COUT);
        const float4* e2 = (const float4*)(h2b + (size_t)si[2][q + 1] * COUT);
        float4* opA = (float4*)(out + (size_t)(q0 + q) * COUT);
        float4* opB = (float4*)(out + (size_t)(q0 + q + 1) * COUT);
#pragma unroll
        for (int c = 0; c < 2; c++) {
            int cc = lane + c * 32;
            float4 vA  = opA[cc];
            float4 t0A = f0[cc];
            float4 t1A = f1[cc];
            float4 t2A = f2[cc];
            float4 vB  = opB[cc];
            float4 t0B = e0[cc];
            float4 t1B = e1[cc];
            float4 t2B = e2[cc];
            vA.x = fmaf(a2, t2A.x, fmaf(a1, t1A.x, fmaf(a0, t0A.x, vA.x)));
            vA.y = fmaf(a2, t2A.y, fmaf(a1, t1A.y, fmaf(a0, t0A.y, vA.y)));
            vA.z = fmaf(a2, t2A.z, fmaf(a1, t1A.z, fmaf(a0, t0A.z, vA.z)));
            vA.w = fmaf(a2, t2A.w, fmaf(a1, t1A.w, fmaf(a0, t0A.w, vA.w)));
            opA[cc] = vA;
            vB.x = fmaf(d2, t2B.x, fmaf(d1, t1B.x, fmaf(d0, t0B.x, vB.x)));
            vB.y = fmaf(d2, t2B.y, fmaf(d1, t1B.y, fmaf(d0, t0B.y, vB.y)));
            vB.z = fmaf(d2, t2B.z, fmaf(d1, t1B.z, fmaf(d0, t0B.z, vB.z)));
            vB.w = fmaf(d2, t2B.w, fmaf(d1, t1B.w, fmaf(d0, t0B.w, vB.w)));
            opB[cc] = vB;
        }
    }
}

// ---------------------------------------------------------------------------
extern "C" void kernel_launch(void* const* d_in, const int* in_sizes, int n_in,
                              void* d_out, int out_size)
{
    const float* p1  = (const float*)d_in[0];
    const float* x1  = (const float*)d_in[1];
    const float* p2  = (const float*)d_in[2];
    const float* x2  = (const float*)d_in[3];
    const float* W1  = (const float*)d_in[4];
    const float* b1p = (const float*)d_in[5];
    const float* g1p = (const float*)d_in[6];
    const float* be1 = (const float*)d_in[7];
    const float* m1p = (const float*)d_in[8];
    const float* v1p = (const float*)d_in[9];
    const float* W2  = (const float*)d_in[10];
    const float* b2p = (const float*)d_in[11];
    const float* g2p = (const float*)d_in[12];
    const float* be2 = (const float*)d_in[13];
    const float* m2p = (const float*)d_in[14];
    const float* v2p = (const float*)d_in[15];
    float* out = (float*)d_out;

    float* h2ptr = nullptr;
    cudaGetSymbolAddress((void**)&h2ptr, g_h2);

    const int SMEM_BYTES = 2 * STAGE_BYTES;   // 80 KB
    cudaFuncSetAttribute(gemm_mma, cudaFuncAttributeMaxDynamicSharedMemorySize, SMEM_BYTES);

    // branch 1: h1 -> out  (M=65536, K=256)
    gemm_mma<<<dim3(N1_TOT / 128, 2), 256, SMEM_BYTES>>>(x1, W1, b1p, g1p, be1, m1p, v1p, out, COUT);

    // branch 2: h2 -> scratch  (M=16384, K=512)
    gemm_mma<<<dim3(N2_TOT / 128, 2), 256, SMEM_BYTES>>>(x2, W2, b2p, g2p, be2, m2p, v2p, h2ptr, CIN);

    // kNN interpolation + add
    interp_kernel<<<N1_TOT / 256, 256>>>(p1, p2, h2ptr, out);
}